// round 2
// baseline (speedup 1.0000x reference)
#include <cuda_runtime.h>
#include <cuda_bf16.h>
#include <math.h>

#define BB    32
#define T_DIM 2048
#define DIN   1024
#define DH    64
#define DC    16
#define KW    7
#define NT    2

// Emission tiling
#define TT 122          // output timesteps per CTA
#define RR 128          // h1 rows per CTA (TT + 6 halo)
#define KC 64           // K chunk

// Scratch (allocation-free rule: __device__ globals)
__device__ __align__(16) float g_W1t[DIN * DH];          // W1 transposed [k][h]
__device__ __align__(16) float g_emis[BB * T_DIM * 2];   // emissions [b][t][n]

// ---------------------------------------------------------------------------
// Kernel 0: transpose W1 [DH][DIN] -> [DIN][DH] for coalesced GEMM loads
// ---------------------------------------------------------------------------
__global__ void w1_transpose_kernel(const float* __restrict__ W1) {
    int i = blockIdx.x * 256 + threadIdx.x;
    if (i < DIN * DH) {
        int h = i & (DH - 1);
        int k = i >> 6;
        g_W1t[i] = W1[h * DIN + k];
    }
}

// ---------------------------------------------------------------------------
// Kernel 1: fused emission:  relu(x@W1^T+b1) -> conv1d(K=7,pad3)+bc,relu -> @W2^T+b2
// One CTA = one (batch, 122-timestep tile). 256 threads.
// Dynamic smem layout:
//   xs : [RR][KC+1] floats (33280 B)  -- x k-chunk tile, later reused as h1 tile
//   wb : 7168 floats (28672 B)        -- W1 chunk [KC][DH] during GEMM (first 16 KB),
//                                        then conv weights [KW][DH][DC]
// ---------------------------------------------------------------------------
#define SMEM_FLOATS (RR * (KC + 1) + KW * DH * DC)
#define SMEM_BYTES  (SMEM_FLOATS * 4)

__global__ void __launch_bounds__(256, 2)
emission_kernel(const float* __restrict__ x,
                const float* __restrict__ b1,
                const float* __restrict__ Wc,
                const float* __restrict__ bc,
                const float* __restrict__ W2,
                const float* __restrict__ b2)
{
    extern __shared__ float sm[];
    float* xs = sm;                    // [RR][KC+1]
    float* wb = sm + RR * (KC + 1);    // ws [KC][DH] / wcs [KW][DH][DC]

    const int tid = threadIdx.x;
    const int tx  = tid & 15;          // col group (4 cols each)
    const int ty  = tid >> 4;          // row group (8 rows each)
    const int b   = blockIdx.y;
    const int t0  = blockIdx.x * TT;
    const int t_base = t0 - 3;
    const float* xb = x + (size_t)b * T_DIM * DIN;

    float acc[8][4];
#pragma unroll
    for (int i = 0; i < 8; i++)
#pragma unroll
        for (int j = 0; j < 4; j++) acc[i][j] = 0.f;

    for (int k0 = 0; k0 < DIN; k0 += KC) {
        // ---- load x tile: 128 rows x 64 cols = 2048 float4 ----
#pragma unroll
        for (int it = 0; it < 8; it++) {
            int idx = tid + it * 256;
            int r = idx >> 4, q = idx & 15;
            int t = t_base + r;
            float4 v = make_float4(0.f, 0.f, 0.f, 0.f);
            if (t >= 0 && t < T_DIM)
                v = *(const float4*)(xb + (size_t)t * DIN + k0 + q * 4);
            float* dst = xs + r * (KC + 1) + q * 4;
            dst[0] = v.x; dst[1] = v.y; dst[2] = v.z; dst[3] = v.w;
        }
        // ---- load W1t chunk: ws[kk][h], 64x64 = 1024 float4, coalesced ----
#pragma unroll
        for (int it = 0; it < 4; it++) {
            int idx = tid + it * 256;
            int kk = idx >> 4, hq = idx & 15;
            float4 v = *(const float4*)(g_W1t + (size_t)(k0 + kk) * DH + hq * 4);
            *(float4*)(wb + kk * DH + hq * 4) = v;
        }
        __syncthreads();

        // ---- 128x64 += 128x64 * 64x64 micro-tiled FMA ----
#pragma unroll 16
        for (int kk = 0; kk < KC; kk++) {
            float xv[8];
#pragma unroll
            for (int i = 0; i < 8; i++) xv[i] = xs[(ty * 8 + i) * (KC + 1) + kk];
            float4 w4 = *(const float4*)(wb + kk * DH + tx * 4);
            float wv[4] = {w4.x, w4.y, w4.z, w4.w};
#pragma unroll
            for (int i = 0; i < 8; i++)
#pragma unroll
                for (int j = 0; j < 4; j++)
                    acc[i][j] = fmaf(xv[i], wv[j], acc[i][j]);
        }
        __syncthreads();
    }

    // ---- epilogue: h1 = relu(acc + b1) (0 for out-of-range rows = conv zero-pad)
    // written back into xs region; simultaneously load conv weights into wb ----
    {
        float bv[4];
#pragma unroll
        for (int j = 0; j < 4; j++) bv[j] = __ldg(b1 + tx * 4 + j);
#pragma unroll
        for (int i = 0; i < 8; i++) {
            int r = ty * 8 + i;
            int t = t_base + r;
            bool valid = (t >= 0 && t < T_DIM);
#pragma unroll
            for (int j = 0; j < 4; j++) {
                float h = valid ? fmaxf(acc[i][j] + bv[j], 0.f) : 0.f;
                xs[r * (KC + 1) + tx * 4 + j] = h;
            }
        }
        // wcs[k][h][c] <- Wc[c][h][k]
        for (int d = tid; d < KW * DH * DC; d += 256) {
            int c = d & 15;
            int h = (d >> 4) & 63;
            int k = d >> 10;
            wb[d] = __ldg(Wc + (c * DH + h) * KW + k);
        }
    }
    __syncthreads();

    // ---- conv (K=7, 64ch -> 16ch) + relu + 16->2 projection, one thread per t ----
    if (tid < TT) {
        int t = t0 + tid;
        if (t < T_DIM) {
            float hc[DC];
#pragma unroll
            for (int c = 0; c < DC; c++) hc[c] = 0.f;
#pragma unroll
            for (int k = 0; k < KW; k++) {
                const float* hrow = xs + (tid + k) * (KC + 1);
                const float* wrow = wb + k * DH * DC;
#pragma unroll 8
                for (int h = 0; h < DH; h++) {
                    float v = hrow[h];
                    const float* wp = wrow + h * DC;
                    float4 w0 = *(const float4*)(wp);
                    float4 w1 = *(const float4*)(wp + 4);
                    float4 w2 = *(const float4*)(wp + 8);
                    float4 w3 = *(const float4*)(wp + 12);
                    hc[0]  = fmaf(v, w0.x, hc[0]);  hc[1]  = fmaf(v, w0.y, hc[1]);
                    hc[2]  = fmaf(v, w0.z, hc[2]);  hc[3]  = fmaf(v, w0.w, hc[3]);
                    hc[4]  = fmaf(v, w1.x, hc[4]);  hc[5]  = fmaf(v, w1.y, hc[5]);
                    hc[6]  = fmaf(v, w1.z, hc[6]);  hc[7]  = fmaf(v, w1.w, hc[7]);
                    hc[8]  = fmaf(v, w2.x, hc[8]);  hc[9]  = fmaf(v, w2.y, hc[9]);
                    hc[10] = fmaf(v, w2.z, hc[10]); hc[11] = fmaf(v, w2.w, hc[11]);
                    hc[12] = fmaf(v, w3.x, hc[12]); hc[13] = fmaf(v, w3.y, hc[13]);
                    hc[14] = fmaf(v, w3.z, hc[14]); hc[15] = fmaf(v, w3.w, hc[15]);
                }
            }
            float e0 = __ldg(b2 + 0), e1 = __ldg(b2 + 1);
#pragma unroll
            for (int c = 0; c < DC; c++) {
                float hv = fmaxf(hc[c] + __ldg(bc + c), 0.f);
                e0 = fmaf(hv, __ldg(W2 + c),      e0);
                e1 = fmaf(hv, __ldg(W2 + DC + c), e1);
            }
            *(float2*)(g_emis + ((size_t)b * T_DIM + t) * 2) = make_float2(e0, e1);
        }
    }
}

// ---------------------------------------------------------------------------
// Kernel 2: zero the scalar output
// ---------------------------------------------------------------------------
__global__ void zero_out_kernel(float* out) { *out = 0.f; }

// ---------------------------------------------------------------------------
// Kernel 3: CRF NLL. One CTA per batch. The forward scan is an ordered product
// of 2x2 matrices in the log semiring -> parallel tree reduction.
// M_t[i][j] = mask[t] ? trans[i][j] + emis[t][j] : Identity (diag 0, off -1e30)
// mask arrives as int32 (harness materializes bool as int32).
// ---------------------------------------------------------------------------
__device__ __forceinline__ float lse2(float a, float b) {
    float mx = fmaxf(a, b);
    float mn = fminf(a, b);
    return mx + log1pf(__expf(mn - mx));
}

__global__ void __launch_bounds__(256)
crf_kernel(const int* __restrict__ mask,
           const int* __restrict__ labels,
           const float* __restrict__ start_t,
           const float* __restrict__ end_t,
           const float* __restrict__ trans,
           float* __restrict__ out)
{
    __shared__ float sP[256][4];
    __shared__ float sNum[256];
    __shared__ int   sCnt[256];

    const int b = blockIdx.x, tid = threadIdx.x;
    const float* em = g_emis + (size_t)b * T_DIM * 2;
    const int* mk = mask + (size_t)b * T_DIM;
    const int* lb = labels + (size_t)b * T_DIM;

    const float t00 = trans[0], t01 = trans[1], t10 = trans[2], t11 = trans[3];

    float P00 = 0.f, P01 = -1e30f, P10 = -1e30f, P11 = 0.f;  // identity
    float num = 0.f;
    int cnt = 0;

    int s = 1 + tid * 8;
    int e = min(s + 8, T_DIM);
    for (int t = s; t < e; t++) {
        if (mk[t] != 0) {
            float2 ev = ((const float2*)em)[t];
            cnt++;
            int lp = lb[t - 1], lc = lb[t];
            num += trans[lp * 2 + lc] + (lc ? ev.y : ev.x);
            float M00 = t00 + ev.x, M01 = t01 + ev.y;
            float M10 = t10 + ev.x, M11 = t11 + ev.y;
            float c00 = lse2(P00 + M00, P01 + M10);
            float c01 = lse2(P00 + M01, P01 + M11);
            float c10 = lse2(P10 + M00, P11 + M10);
            float c11 = lse2(P10 + M01, P11 + M11);
            P00 = c00; P01 = c01; P10 = c10; P11 = c11;
        }
    }

    sP[tid][0] = P00; sP[tid][1] = P01; sP[tid][2] = P10; sP[tid][3] = P11;
    sNum[tid] = num; sCnt[tid] = cnt;
    __syncthreads();

    // ordered tree combine: left ⊗ right
    for (int off = 128; off > 0; off >>= 1) {
        if (tid < off) {
            float A00 = sP[tid][0], A01 = sP[tid][1], A10 = sP[tid][2], A11 = sP[tid][3];
            float B00 = sP[tid + off][0], B01 = sP[tid + off][1];
            float B10 = sP[tid + off][2], B11 = sP[tid + off][3];
            sP[tid][0] = lse2(A00 + B00, A01 + B10);
            sP[tid][1] = lse2(A00 + B01, A01 + B11);
            sP[tid][2] = lse2(A10 + B00, A11 + B10);
            sP[tid][3] = lse2(A10 + B01, A11 + B11);
            sNum[tid] += sNum[tid + off];
            sCnt[tid] += sCnt[tid + off];
        }
        __syncthreads();
    }

    if (tid == 0) {
        float a0 = start_t[0] + em[0];
        float a1 = start_t[1] + em[1];
        float f0 = lse2(a0 + sP[0][0], a1 + sP[0][2]);
        float f1 = lse2(a0 + sP[0][1], a1 + sP[0][3]);
        float logZ = lse2(f0 + end_t[0], f1 + end_t[1]);

        int total = sCnt[0] + (mk[0] != 0 ? 1 : 0);
        int last = max(total - 1, 0);
        int l0 = lb[0];
        float numT = sNum[0] + start_t[l0] + (l0 ? em[1] : em[0]) + end_t[lb[last]];
        atomicAdd(out, logZ - numT);   // loss = sum_b (logZ - num)
    }
}

// ---------------------------------------------------------------------------
extern "C" void kernel_launch(void* const* d_in, const int* in_sizes, int n_in,
                              void* d_out, int out_size) {
    const float* x      = (const float*)d_in[0];
    const int*   mask   = (const int*)d_in[1];    // bool -> int32 per harness dtypes
    const int*   labels = (const int*)d_in[2];
    const float* W1     = (const float*)d_in[3];
    const float* b1     = (const float*)d_in[4];
    const float* Wc     = (const float*)d_in[5];
    const float* bc     = (const float*)d_in[6];
    const float* W2     = (const float*)d_in[7];
    const float* b2     = (const float*)d_in[8];
    const float* st     = (const float*)d_in[9];
    const float* et     = (const float*)d_in[10];
    const float* tr     = (const float*)d_in[11];
    float* out = (float*)d_out;

    (void)in_sizes; (void)n_in; (void)out_size;

    cudaFuncSetAttribute(emission_kernel,
                         cudaFuncAttributeMaxDynamicSharedMemorySize, SMEM_BYTES);

    w1_transpose_kernel<<<(DIN * DH + 255) / 256, 256>>>(W1);

    dim3 egrid((T_DIM + TT - 1) / TT, BB);   // 17 x 32
    emission_kernel<<<egrid, 256, SMEM_BYTES>>>(x, b1, Wc, bc, W2, b2);

    zero_out_kernel<<<1, 1>>>(out);
    crf_kernel<<<BB, 256>>>(mask, labels, st, et, tr, out);
}

// round 3
// speedup vs baseline: 1.8445x; 1.8445x over previous
#include <cuda_runtime.h>
#include <cuda_bf16.h>
#include <math.h>

#define BB    32
#define T_DIM 2048
#define DIN   1024
#define DH    64
#define DC    16
#define KW    7
#define NT    2

// Emission tiling
#define TT 122          // output timesteps per CTA
#define RR 128          // h1 rows per CTA (TT + 6 halo)
#define KC 64           // K chunk per smem stage

// smem pitches (floats), chosen for conflict-free mma fragment loads
#define X_P 68          // 68 % 32 == 4  -> A-frag banks = 4*(lane/4)+lane%4 (distinct)
#define W_P 72          // 72 % 32 == 8  -> B-frag banks = 8*(lane%4)+lane/4 (distinct)
#define H_P 65          // conv phase: bank = tid + h (distinct per h)

// phase1: xs[128][68] = 8704 fl, ws[64][72] = 4608 fl  -> 13312 fl
// phase2: hs[128][65] = 8320 fl, wcs[7*64*16] = 7168 fl -> 15488 fl
#define SMEM_FLOATS 15488
#define SMEM_BYTES  (SMEM_FLOATS * 4)
#define HS_OFF      8320

// Scratch (allocation-free rule: __device__ globals)
__device__ __align__(16) float g_W1t[DIN * DH];          // W1 transposed [k][h]
__device__ __align__(16) float g_emis[BB * T_DIM * 2];   // emissions [b][t][n]

// ---------------------------------------------------------------------------
// tf32 helpers
// ---------------------------------------------------------------------------
__device__ __forceinline__ unsigned cvt_tf32(float f) {
    unsigned u;
    asm("cvt.rna.tf32.f32 %0, %1;" : "=r"(u) : "f"(f));
    return u;
}

__device__ __forceinline__ void mma_tf32(float* d,
                                         unsigned a0, unsigned a1, unsigned a2, unsigned a3,
                                         unsigned b0, unsigned b1) {
    asm volatile("mma.sync.aligned.m16n8k8.row.col.f32.tf32.tf32.f32 "
                 "{%0,%1,%2,%3}, {%4,%5,%6,%7}, {%8,%9}, {%0,%1,%2,%3};"
                 : "+f"(d[0]), "+f"(d[1]), "+f"(d[2]), "+f"(d[3])
                 : "r"(a0), "r"(a1), "r"(a2), "r"(a3), "r"(b0), "r"(b1));
}

// ---------------------------------------------------------------------------
// Kernel 0: transpose W1 [DH][DIN] -> [DIN][DH]; thread (0,0) zeros the output
// ---------------------------------------------------------------------------
__global__ void w1_transpose_kernel(const float* __restrict__ W1, float* out) {
    int i = blockIdx.x * 256 + threadIdx.x;
    if (i == 0) *out = 0.f;
    if (i < DIN * DH) {
        int h = i & (DH - 1);
        int k = i >> 6;
        g_W1t[i] = W1[h * DIN + k];
    }
}

// ---------------------------------------------------------------------------
// Kernel 1: fused emission using tf32 tensor-core GEMM.
// One CTA = one (batch, 122-timestep tile). 256 threads = 8 warps.
// Warp w owns rows [16w, 16w+16) x all 64 h-cols = 8 m16n8k8 atoms.
// ---------------------------------------------------------------------------
__global__ void __launch_bounds__(256, 2)
emission_kernel(const float* __restrict__ x,
                const float* __restrict__ b1,
                const float* __restrict__ Wc,
                const float* __restrict__ bc,
                const float* __restrict__ W2,
                const float* __restrict__ b2)
{
    extern __shared__ float sm[];
    float* xs = sm;                 // phase1 tf32 bits [RR][X_P]
    float* ws = sm + RR * X_P;      // phase1 tf32 bits [KC][W_P]
    float* hs = sm;                 // phase2 h1 tile [RR][H_P]
    float* wcs = sm + HS_OFF;       // phase2 conv weights [KW][DH][DC]

    const int tid  = threadIdx.x;
    const int lane = tid & 31;
    const int warp = tid >> 5;
    const int qr   = lane >> 2;     // 0..7
    const int qc   = lane & 3;      // 0..3
    const int b    = blockIdx.y;
    const int t0   = blockIdx.x * TT;
    const int t_base = t0 - 3;
    const float* xb = x + (size_t)b * T_DIM * DIN;

    float acc[8][4];
#pragma unroll
    for (int j = 0; j < 8; j++)
#pragma unroll
        for (int i = 0; i < 4; i++) acc[j][i] = 0.f;

    for (int k0 = 0; k0 < DIN; k0 += KC) {
        // ---- load x tile (128 x 64), cvt to tf32 at store ----
#pragma unroll
        for (int it = 0; it < 8; it++) {
            int idx = tid + it * 256;
            int r = idx >> 4, q = idx & 15;     // 16 float4 per row
            int t = t_base + r;
            float4 v = make_float4(0.f, 0.f, 0.f, 0.f);
            if (t >= 0 && t < T_DIM)
                v = *(const float4*)(xb + (size_t)t * DIN + k0 + q * 4);
            uint4 u;
            u.x = cvt_tf32(v.x); u.y = cvt_tf32(v.y);
            u.z = cvt_tf32(v.z); u.w = cvt_tf32(v.w);
            *(uint4*)(xs + r * X_P + q * 4) = u;
        }
        // ---- load W1t chunk (64 x 64), cvt to tf32 at store ----
#pragma unroll
        for (int it = 0; it < 4; it++) {
            int idx = tid + it * 256;
            int kk = idx >> 4, q = idx & 15;
            float4 v = *(const float4*)(g_W1t + (size_t)(k0 + kk) * DH + q * 4);
            uint4 u;
            u.x = cvt_tf32(v.x); u.y = cvt_tf32(v.y);
            u.z = cvt_tf32(v.z); u.w = cvt_tf32(v.w);
            *(uint4*)(ws + kk * W_P + q * 4) = u;
        }
        __syncthreads();

        // ---- 8 k-steps of m16n8k8 per chunk ----
        const unsigned* xu = (const unsigned*)xs;
        const unsigned* wu = (const unsigned*)ws;
        const int r0 = warp * 16 + qr;
#pragma unroll
        for (int ks = 0; ks < KC / 8; ks++) {
            int k = ks * 8;
            unsigned a0 = xu[r0 * X_P + k + qc];
            unsigned a1 = xu[(r0 + 8) * X_P + k + qc];
            unsigned a2 = xu[r0 * X_P + k + qc + 4];
            unsigned a3 = xu[(r0 + 8) * X_P + k + qc + 4];
#pragma unroll
            for (int j = 0; j < 8; j++) {
                unsigned b0 = wu[(k + qc) * W_P + j * 8 + qr];
                unsigned b1r = wu[(k + 4 + qc) * W_P + j * 8 + qr];
                mma_tf32(acc[j], a0, a1, a2, a3, b0, b1r);
            }
        }
        __syncthreads();
    }

    // ---- epilogue: h1 = relu(acc + b1); zero for out-of-range rows ----
    {
        const int r0 = warp * 16 + qr;
        const int r1 = r0 + 8;
        const int tA = t_base + r0, tB = t_base + r1;
        const bool vA = (tA >= 0 && tA < T_DIM);
        const bool vB = (tB >= 0 && tB < T_DIM);
#pragma unroll
        for (int j = 0; j < 8; j++) {
            int c0 = j * 8 + 2 * qc, c1 = c0 + 1;
            float bv0 = __ldg(b1 + c0), bv1 = __ldg(b1 + c1);
            hs[r0 * H_P + c0] = vA ? fmaxf(acc[j][0] + bv0, 0.f) : 0.f;
            hs[r0 * H_P + c1] = vA ? fmaxf(acc[j][1] + bv1, 0.f) : 0.f;
            hs[r1 * H_P + c0] = vB ? fmaxf(acc[j][2] + bv0, 0.f) : 0.f;
            hs[r1 * H_P + c1] = vB ? fmaxf(acc[j][3] + bv1, 0.f) : 0.f;
        }
        // wcs[k][h][c] <- Wc[c][h][k]
        for (int d = tid; d < KW * DH * DC; d += 256) {
            int c = d & 15;
            int h = (d >> 4) & 63;
            int k = d >> 10;
            wcs[d] = __ldg(Wc + (c * DH + h) * KW + k);
        }
    }
    __syncthreads();

    // ---- conv (K=7, 64ch -> 16ch) + relu + 16->2 projection, one thread per t ----
    if (tid < TT) {
        int t = t0 + tid;
        if (t < T_DIM) {
            float hc[DC];
#pragma unroll
            for (int c = 0; c < DC; c++) hc[c] = 0.f;
#pragma unroll
            for (int k = 0; k < KW; k++) {
                const float* hrow = hs + (tid + k) * H_P;
                const float* wrow = wcs + k * DH * DC;
#pragma unroll 8
                for (int h = 0; h < DH; h++) {
                    float v = hrow[h];
                    const float* wp = wrow + h * DC;
                    float4 w0 = *(const float4*)(wp);
                    float4 w1 = *(const float4*)(wp + 4);
                    float4 w2 = *(const float4*)(wp + 8);
                    float4 w3 = *(const float4*)(wp + 12);
                    hc[0]  = fmaf(v, w0.x, hc[0]);  hc[1]  = fmaf(v, w0.y, hc[1]);
                    hc[2]  = fmaf(v, w0.z, hc[2]);  hc[3]  = fmaf(v, w0.w, hc[3]);
                    hc[4]  = fmaf(v, w1.x, hc[4]);  hc[5]  = fmaf(v, w1.y, hc[5]);
                    hc[6]  = fmaf(v, w1.z, hc[6]);  hc[7]  = fmaf(v, w1.w, hc[7]);
                    hc[8]  = fmaf(v, w2.x, hc[8]);  hc[9]  = fmaf(v, w2.y, hc[9]);
                    hc[10] = fmaf(v, w2.z, hc[10]); hc[11] = fmaf(v, w2.w, hc[11]);
                    hc[12] = fmaf(v, w3.x, hc[12]); hc[13] = fmaf(v, w3.y, hc[13]);
                    hc[14] = fmaf(v, w3.z, hc[14]); hc[15] = fmaf(v, w3.w, hc[15]);
                }
            }
            float e0 = __ldg(b2 + 0), e1 = __ldg(b2 + 1);
#pragma unroll
            for (int c = 0; c < DC; c++) {
                float hv = fmaxf(hc[c] + __ldg(bc + c), 0.f);
                e0 = fmaf(hv, __ldg(W2 + c),      e0);
                e1 = fmaf(hv, __ldg(W2 + DC + c), e1);
            }
            *(float2*)(g_emis + ((size_t)b * T_DIM + t) * 2) = make_float2(e0, e1);
        }
    }
}

// ---------------------------------------------------------------------------
// Kernel 2: CRF NLL. One CTA per batch; forward scan = ordered product of 2x2
// log-semiring matrices -> tree reduction. Loads hoisted for MLP.
// ---------------------------------------------------------------------------
__device__ __forceinline__ float lse2(float a, float b) {
    float mx = fmaxf(a, b);
    float mn = fminf(a, b);
    return mx + log1pf(__expf(mn - mx));
}

__global__ void __launch_bounds__(256)
crf_kernel(const int* __restrict__ mask,
           const int* __restrict__ labels,
           const float* __restrict__ start_t,
           const float* __restrict__ end_t,
           const float* __restrict__ trans,
           float* __restrict__ out)
{
    __shared__ float sP[256][4];
    __shared__ float sNum[256];
    __shared__ int   sCnt[256];

    const int b = blockIdx.x, tid = threadIdx.x;
    const float* em = g_emis + (size_t)b * T_DIM * 2;
    const int* mk = mask + (size_t)b * T_DIM;
    const int* lb = labels + (size_t)b * T_DIM;

    const float t00 = trans[0], t01 = trans[1], t10 = trans[2], t11 = trans[3];

    // prefetch this thread's 8-timestep slab (batched loads -> MLP)
    const int s = 1 + tid * 8;
    float2 ev[8]; int mv[8], lv[8];
#pragma unroll
    for (int i = 0; i < 8; i++) {
        int t = s + i;
        bool ok = (t < T_DIM);
        mv[i] = ok ? mk[t] : 0;
        lv[i] = ok ? lb[t] : 0;
        ev[i] = ok ? ((const float2*)em)[t] : make_float2(0.f, 0.f);
    }
    int lprev = lb[s - 1];

    float P00 = 0.f, P01 = -1e30f, P10 = -1e30f, P11 = 0.f;  // identity
    float num = 0.f;
    int cnt = 0;

#pragma unroll
    for (int i = 0; i < 8; i++) {
        if (mv[i] != 0) {
            cnt++;
            int lc = lv[i];
            float tv = lprev ? (lc ? t11 : t10) : (lc ? t01 : t00);
            num += tv + (lc ? ev[i].y : ev[i].x);
            float M00 = t00 + ev[i].x, M01 = t01 + ev[i].y;
            float M10 = t10 + ev[i].x, M11 = t11 + ev[i].y;
            float c00 = lse2(P00 + M00, P01 + M10);
            float c01 = lse2(P00 + M01, P01 + M11);
            float c10 = lse2(P10 + M00, P11 + M10);
            float c11 = lse2(P10 + M01, P11 + M11);
            P00 = c00; P01 = c01; P10 = c10; P11 = c11;
        }
        lprev = lv[i];
    }

    sP[tid][0] = P00; sP[tid][1] = P01; sP[tid][2] = P10; sP[tid][3] = P11;
    sNum[tid] = num; sCnt[tid] = cnt;
    __syncthreads();

    for (int off = 128; off > 0; off >>= 1) {
        if (tid < off) {
            float A00 = sP[tid][0], A01 = sP[tid][1], A10 = sP[tid][2], A11 = sP[tid][3];
            float B00 = sP[tid + off][0], B01 = sP[tid + off][1];
            float B10 = sP[tid + off][2], B11 = sP[tid + off][3];
            sP[tid][0] = lse2(A00 + B00, A01 + B10);
            sP[tid][1] = lse2(A00 + B01, A01 + B11);
            sP[tid][2] = lse2(A10 + B00, A11 + B10);
            sP[tid][3] = lse2(A10 + B01, A11 + B11);
            sNum[tid] += sNum[tid + off];
            sCnt[tid] += sCnt[tid + off];
        }
        __syncthreads();
    }

    if (tid == 0) {
        float a0 = start_t[0] + em[0];
        float a1 = start_t[1] + em[1];
        float f0 = lse2(a0 + sP[0][0], a1 + sP[0][2]);
        float f1 = lse2(a0 + sP[0][1], a1 + sP[0][3]);
        float logZ = lse2(f0 + end_t[0], f1 + end_t[1]);

        int total = sCnt[0] + (mk[0] != 0 ? 1 : 0);
        int last = max(total - 1, 0);
        int l0 = lb[0];
        float numT = sNum[0] + start_t[l0] + (l0 ? em[1] : em[0]) + end_t[lb[last]];
        atomicAdd(out, logZ - numT);   // loss = sum_b (logZ - num)
    }
}

// ---------------------------------------------------------------------------
extern "C" void kernel_launch(void* const* d_in, const int* in_sizes, int n_in,
                              void* d_out, int out_size) {
    const float* x      = (const float*)d_in[0];
    const int*   mask   = (const int*)d_in[1];    // bool -> int32 per harness dtypes
    const int*   labels = (const int*)d_in[2];
    const float* W1     = (const float*)d_in[3];
    const float* b1     = (const float*)d_in[4];
    const float* Wc     = (const float*)d_in[5];
    const float* bc     = (const float*)d_in[6];
    const float* W2     = (const float*)d_in[7];
    const float* b2     = (const float*)d_in[8];
    const float* st     = (const float*)d_in[9];
    const float* et     = (const float*)d_in[10];
    const float* tr     = (const float*)d_in[11];
    float* out = (float*)d_out;

    (void)in_sizes; (void)n_in; (void)out_size;

    cudaFuncSetAttribute(emission_kernel,
                         cudaFuncAttributeMaxDynamicSharedMemorySize, SMEM_BYTES);

    w1_transpose_kernel<<<(DIN * DH + 255) / 256, 256>>>(W1, out);

    dim3 egrid((T_DIM + TT - 1) / TT, BB);   // 17 x 32
    emission_kernel<<<egrid, 256, SMEM_BYTES>>>(x, b1, Wc, bc, W2, b2);

    crf_kernel<<<BB, 256>>>(mask, labels, st, et, tr, out);
}

// round 4
// speedup vs baseline: 2.1784x; 1.1810x over previous
#include <cuda_runtime.h>
#include <cuda_bf16.h>
#include <math.h>

#define BB    32
#define T_DIM 2048
#define DIN   1024
#define DH    64
#define DC    16
#define KW    7
#define NT    2

// Emission tiling
#define TT 122          // output timesteps per CTA
#define RR 128          // h1 rows per CTA (TT + 6 halo)
#define KC 64           // K chunk per smem stage

// smem pitches (floats), chosen for conflict-free mma fragment loads
#define X_P 68          // 68 % 32 == 4  -> A-frag banks = 4*(lane/4)+lane%4 (distinct)
#define W_P 72          // 72 % 32 == 8  -> B-frag banks = 8*(lane%4)+lane/4 (distinct)
#define C_P 24          // conv W: 24*qc mod 32 = {0,24,16,8} -> conflict-free B-frags

// layout: xs[128][68]=8704 | ws[64][72]=4608 | wcs[7][64][24]=10752
#define WS_OFF   (RR * X_P)
#define WCS_OFF  (WS_OFF + KC * W_P)
#define SMEM_FLOATS (WCS_OFF + KW * DH * C_P)
#define SMEM_BYTES  (SMEM_FLOATS * 4)

// Scratch (allocation-free rule: __device__ globals)
__device__ __align__(16) float g_W1t[DIN * DH];          // W1 transposed [k][h]
__device__ __align__(16) float g_emis[BB * T_DIM * 2];   // emissions [b][t][n]

// ---------------------------------------------------------------------------
// tf32 helpers
// ---------------------------------------------------------------------------
__device__ __forceinline__ unsigned cvt_tf32(float f) {
    unsigned u;
    asm("cvt.rna.tf32.f32 %0, %1;" : "=r"(u) : "f"(f));
    return u;
}

__device__ __forceinline__ void mma_tf32(float* d,
                                         unsigned a0, unsigned a1, unsigned a2, unsigned a3,
                                         unsigned b0, unsigned b1) {
    asm volatile("mma.sync.aligned.m16n8k8.row.col.f32.tf32.tf32.f32 "
                 "{%0,%1,%2,%3}, {%4,%5,%6,%7}, {%8,%9}, {%0,%1,%2,%3};"
                 : "+f"(d[0]), "+f"(d[1]), "+f"(d[2]), "+f"(d[3])
                 : "r"(a0), "r"(a1), "r"(a2), "r"(a3), "r"(b0), "r"(b1));
}

// ---------------------------------------------------------------------------
// Kernel 0: tiled transpose W1 [DH][DIN] -> [DIN][DH]; also zeroes the output
// ---------------------------------------------------------------------------
__global__ void w1_transpose_kernel(const float* __restrict__ W1, float* out) {
    __shared__ float tile[32][33];
    const int k0 = blockIdx.x * 32;   // DIN
    const int h0 = blockIdx.y * 32;   // DH
    const int tx = threadIdx.x, ty = threadIdx.y;
    if (blockIdx.x == 0 && blockIdx.y == 0 && tx == 0 && ty == 0) *out = 0.f;
#pragma unroll
    for (int i = 0; i < 32; i += 8)
        tile[ty + i][tx] = W1[(size_t)(h0 + ty + i) * DIN + k0 + tx];
    __syncthreads();
#pragma unroll
    for (int i = 0; i < 32; i += 8)
        g_W1t[(size_t)(k0 + ty + i) * DH + h0 + tx] = tile[tx][ty + i];
}

// ---------------------------------------------------------------------------
// Kernel 1: fused emission, all GEMM work on tensor cores (tf32).
//   phase1: h1 = relu(x @ W1^T + b1)     (128x64 per CTA, 16 k-chunks)
//   phase2: conv(K=7) as 7 shifted MMAs  (+bc, relu) + 16->2 projection
// One CTA = one (batch, 122-timestep tile). 256 threads = 8 warps.
// ---------------------------------------------------------------------------
__global__ void __launch_bounds__(256, 2)
emission_kernel(const float* __restrict__ x,
                const float* __restrict__ b1,
                const float* __restrict__ Wc,
                const float* __restrict__ bc,
                const float* __restrict__ W2,
                const float* __restrict__ b2)
{
    extern __shared__ float sm[];
    float* xs  = sm;              // [RR][X_P] x-tile tf32 / later h1 tf32
    float* ws  = sm + WS_OFF;     // [KC][W_P] W1t chunk tf32
    float* wcs = sm + WCS_OFF;    // [KW][DH][C_P] conv weights tf32

    const int tid  = threadIdx.x;
    const int lane = tid & 31;
    const int warp = tid >> 5;
    const int qr   = lane >> 2;     // 0..7
    const int qc   = lane & 3;      // 0..3
    const int b    = blockIdx.y;
    const int t0   = blockIdx.x * TT;
    const int t_base = t0 - 3;
    const float* xb = x + (size_t)b * T_DIM * DIN;

    // ---- preload conv weights: wcs[k][h][c] <- tf32(Wc[c][h][k]) ----
    for (int d = tid; d < KW * DH * DC; d += 256) {
        int c = d & 15;
        int h = (d >> 4) & 63;
        int k = d >> 10;
        wcs[k * (DH * C_P) + h * C_P + c] = __uint_as_float(cvt_tf32(__ldg(Wc + (c * DH + h) * KW + k)));
    }

    float acc[8][4];
#pragma unroll
    for (int j = 0; j < 8; j++)
#pragma unroll
        for (int i = 0; i < 4; i++) acc[j][i] = 0.f;

    for (int k0 = 0; k0 < DIN; k0 += KC) {
        // ---- load x tile (128 x 64), cvt to tf32 at store ----
#pragma unroll
        for (int it = 0; it < 8; it++) {
            int idx = tid + it * 256;
            int r = idx >> 4, q = idx & 15;     // 16 float4 per row
            int t = t_base + r;
            float4 v = make_float4(0.f, 0.f, 0.f, 0.f);
            if (t >= 0 && t < T_DIM)
                v = *(const float4*)(xb + (size_t)t * DIN + k0 + q * 4);
            uint4 u;
            u.x = cvt_tf32(v.x); u.y = cvt_tf32(v.y);
            u.z = cvt_tf32(v.z); u.w = cvt_tf32(v.w);
            *(uint4*)(xs + r * X_P + q * 4) = u;
        }
        // ---- load W1t chunk (64 x 64), cvt to tf32 at store ----
#pragma unroll
        for (int it = 0; it < 4; it++) {
            int idx = tid + it * 256;
            int kk = idx >> 4, q = idx & 15;
            float4 v = *(const float4*)(g_W1t + (size_t)(k0 + kk) * DH + q * 4);
            uint4 u;
            u.x = cvt_tf32(v.x); u.y = cvt_tf32(v.y);
            u.z = cvt_tf32(v.z); u.w = cvt_tf32(v.w);
            *(uint4*)(ws + kk * W_P + q * 4) = u;
        }
        __syncthreads();

        // ---- 8 k-steps of m16n8k8 per chunk ----
        const unsigned* xu = (const unsigned*)xs;
        const unsigned* wu = (const unsigned*)ws;
        const int r0 = warp * 16 + qr;
#pragma unroll
        for (int ks = 0; ks < KC / 8; ks++) {
            int k = ks * 8;
            unsigned a0 = xu[r0 * X_P + k + qc];
            unsigned a1 = xu[(r0 + 8) * X_P + k + qc];
            unsigned a2 = xu[r0 * X_P + k + qc + 4];
            unsigned a3 = xu[(r0 + 8) * X_P + k + qc + 4];
#pragma unroll
            for (int j = 0; j < 8; j++) {
                unsigned b0 = wu[(k + qc) * W_P + j * 8 + qr];
                unsigned b1r = wu[(k + 4 + qc) * W_P + j * 8 + qr];
                mma_tf32(acc[j], a0, a1, a2, a3, b0, b1r);
            }
        }
        __syncthreads();
    }

    // ---- GEMM epilogue: h1 = relu(acc + b1) stored to xs as tf32 bits ----
    {
        const int r0 = warp * 16 + qr;
        const int r1 = r0 + 8;
        const int tA = t_base + r0, tB = t_base + r1;
        const bool vA = (tA >= 0 && tA < T_DIM);
        const bool vB = (tB >= 0 && tB < T_DIM);
        unsigned* xw = (unsigned*)xs;
#pragma unroll
        for (int j = 0; j < 8; j++) {
            int c0 = j * 8 + 2 * qc, c1 = c0 + 1;
            float bv0 = __ldg(b1 + c0), bv1 = __ldg(b1 + c1);
            xw[r0 * X_P + c0] = cvt_tf32(vA ? fmaxf(acc[j][0] + bv0, 0.f) : 0.f);
            xw[r0 * X_P + c1] = cvt_tf32(vA ? fmaxf(acc[j][1] + bv1, 0.f) : 0.f);
            xw[r1 * X_P + c0] = cvt_tf32(vB ? fmaxf(acc[j][2] + bv0, 0.f) : 0.f);
            xw[r1 * X_P + c1] = cvt_tf32(vB ? fmaxf(acc[j][3] + bv1, 0.f) : 0.f);
        }
    }
    __syncthreads();

    // ---- conv as 7 shifted MMAs: out[r][c] = sum_k sum_h h1[r+k][h]*wc[k][h][c] ----
    float acc2[2][4];
#pragma unroll
    for (int j = 0; j < 2; j++)
#pragma unroll
        for (int i = 0; i < 4; i++) acc2[j][i] = 0.f;

    {
        const unsigned* hu  = (const unsigned*)xs;
        const unsigned* wcu = (const unsigned*)wcs;
        const int wb2 = warp * 16;
#pragma unroll
        for (int k = 0; k < KW; k++) {
            const unsigned* wck = wcu + k * (DH * C_P);
#pragma unroll
            for (int ks = 0; ks < 8; ks++) {
                int hh = ks * 8;
                int ra = wb2 + k + qr;
                // OOB rows (>127, only feeding discarded outputs >=TT) stay
                // inside the smem allocation -> harmless garbage.
                unsigned a0 = hu[ra * X_P + hh + qc];
                unsigned a1 = hu[(ra + 8) * X_P + hh + qc];
                unsigned a2 = hu[ra * X_P + hh + qc + 4];
                unsigned a3 = hu[(ra + 8) * X_P + hh + qc + 4];
                unsigned b0 = wck[(hh + qc) * C_P + qr];
                unsigned b1r = wck[(hh + 4 + qc) * C_P + qr];
                mma_tf32(acc2[0], a0, a1, a2, a3, b0, b1r);
                unsigned c0 = wck[(hh + qc) * C_P + 8 + qr];
                unsigned c1 = wck[(hh + 4 + qc) * C_P + 8 + qr];
                mma_tf32(acc2[1], a0, a1, a2, a3, c0, c1);
            }
        }
    }

    // ---- +bc, relu, project 16->2, reduce across qc, store emissions ----
    {
        float e0a = 0.f, e1a = 0.f, e0b = 0.f, e1b = 0.f;
#pragma unroll
        for (int j = 0; j < 2; j++) {
            int c0 = j * 8 + 2 * qc, c1 = c0 + 1;
            float bc0 = __ldg(bc + c0), bc1 = __ldg(bc + c1);
            float w00 = __ldg(W2 + c0),      w01 = __ldg(W2 + c1);
            float w10 = __ldg(W2 + DC + c0), w11 = __ldg(W2 + DC + c1);
            float hA0 = fmaxf(acc2[j][0] + bc0, 0.f), hA1 = fmaxf(acc2[j][1] + bc1, 0.f);
            float hB0 = fmaxf(acc2[j][2] + bc0, 0.f), hB1 = fmaxf(acc2[j][3] + bc1, 0.f);
            e0a = fmaf(hA0, w00, fmaf(hA1, w01, e0a));
            e1a = fmaf(hA0, w10, fmaf(hA1, w11, e1a));
            e0b = fmaf(hB0, w00, fmaf(hB1, w01, e0b));
            e1b = fmaf(hB0, w10, fmaf(hB1, w11, e1b));
        }
#pragma unroll
        for (int m = 1; m <= 2; m <<= 1) {
            e0a += __shfl_xor_sync(0xffffffffu, e0a, m);
            e1a += __shfl_xor_sync(0xffffffffu, e1a, m);
            e0b += __shfl_xor_sync(0xffffffffu, e0b, m);
            e1b += __shfl_xor_sync(0xffffffffu, e1b, m);
        }
        if (qc == 0) {
            const float bz0 = __ldg(b2 + 0), bz1 = __ldg(b2 + 1);
            int rA = warp * 16 + qr, rB = rA + 8;
            if (rA < TT && t0 + rA < T_DIM)
                *(float2*)(g_emis + ((size_t)b * T_DIM + t0 + rA) * 2) =
                    make_float2(e0a + bz0, e1a + bz1);
            if (rB < TT && t0 + rB < T_DIM)
                *(float2*)(g_emis + ((size_t)b * T_DIM + t0 + rB) * 2) =
                    make_float2(e0b + bz0, e1b + bz1);
        }
    }
}

// ---------------------------------------------------------------------------
// Kernel 2: CRF NLL. One CTA per batch; forward scan = ordered product of 2x2
// log-semiring matrices -> tree reduction. Loads hoisted for MLP.
// ---------------------------------------------------------------------------
__device__ __forceinline__ float lse2(float a, float b) {
    float mx = fmaxf(a, b);
    float mn = fminf(a, b);
    return mx + log1pf(__expf(mn - mx));
}

__global__ void __launch_bounds__(256)
crf_kernel(const int* __restrict__ mask,
           const int* __restrict__ labels,
           const float* __restrict__ start_t,
           const float* __restrict__ end_t,
           const float* __restrict__ trans,
           float* __restrict__ out)
{
    __shared__ float sP[256][4];
    __shared__ float sNum[256];
    __shared__ int   sCnt[256];

    const int b = blockIdx.x, tid = threadIdx.x;
    const float* em = g_emis + (size_t)b * T_DIM * 2;
    const int* mk = mask + (size_t)b * T_DIM;
    const int* lb = labels + (size_t)b * T_DIM;

    const float t00 = trans[0], t01 = trans[1], t10 = trans[2], t11 = trans[3];

    // prefetch this thread's 8-timestep slab (batched loads -> MLP)
    const int s = 1 + tid * 8;
    float2 ev[8]; int mv[8], lv[8];
#pragma unroll
    for (int i = 0; i < 8; i++) {
        int t = s + i;
        bool ok = (t < T_DIM);
        mv[i] = ok ? mk[t] : 0;
        lv[i] = ok ? lb[t] : 0;
        ev[i] = ok ? ((const float2*)em)[t] : make_float2(0.f, 0.f);
    }
    int lprev = lb[s - 1];

    float P00 = 0.f, P01 = -1e30f, P10 = -1e30f, P11 = 0.f;  // identity
    float num = 0.f;
    int cnt = 0;

#pragma unroll
    for (int i = 0; i < 8; i++) {
        if (mv[i] != 0) {
            cnt++;
            int lc = lv[i];
            float tv = lprev ? (lc ? t11 : t10) : (lc ? t01 : t00);
            num += tv + (lc ? ev[i].y : ev[i].x);
            float M00 = t00 + ev[i].x, M01 = t01 + ev[i].y;
            float M10 = t10 + ev[i].x, M11 = t11 + ev[i].y;
            float c00 = lse2(P00 + M00, P01 + M10);
            float c01 = lse2(P00 + M01, P01 + M11);
            float c10 = lse2(P10 + M00, P11 + M10);
            float c11 = lse2(P10 + M01, P11 + M11);
            P00 = c00; P01 = c01; P10 = c10; P11 = c11;
        }
        lprev = lv[i];
    }

    sP[tid][0] = P00; sP[tid][1] = P01; sP[tid][2] = P10; sP[tid][3] = P11;
    sNum[tid] = num; sCnt[tid] = cnt;
    __syncthreads();

    for (int off = 128; off > 0; off >>= 1) {
        if (tid < off) {
            float A00 = sP[tid][0], A01 = sP[tid][1], A10 = sP[tid][2], A11 = sP[tid][3];
            float B00 = sP[tid + off][0], B01 = sP[tid + off][1];
            float B10 = sP[tid + off][2], B11 = sP[tid + off][3];
            sP[tid][0] = lse2(A00 + B00, A01 + B10);
            sP[tid][1] = lse2(A00 + B01, A01 + B11);
            sP[tid][2] = lse2(A10 + B00, A11 + B10);
            sP[tid][3] = lse2(A10 + B01, A11 + B11);
            sNum[tid] += sNum[tid + off];
            sCnt[tid] += sCnt[tid + off];
        }
        __syncthreads();
    }

    if (tid == 0) {
        float a0 = start_t[0] + em[0];
        float a1 = start_t[1] + em[1];
        float f0 = lse2(a0 + sP[0][0], a1 + sP[0][2]);
        float f1 = lse2(a0 + sP[0][1], a1 + sP[0][3]);
        float logZ = lse2(f0 + end_t[0], f1 + end_t[1]);

        int total = sCnt[0] + (mk[0] != 0 ? 1 : 0);
        int last = max(total - 1, 0);
        int l0 = lb[0];
        float numT = sNum[0] + start_t[l0] + (l0 ? em[1] : em[0]) + end_t[lb[last]];
        atomicAdd(out, logZ - numT);   // loss = sum_b (logZ - num)
    }
}

// ---------------------------------------------------------------------------
extern "C" void kernel_launch(void* const* d_in, const int* in_sizes, int n_in,
                              void* d_out, int out_size) {
    const float* x      = (const float*)d_in[0];
    const int*   mask   = (const int*)d_in[1];    // bool -> int32 per harness dtypes
    const int*   labels = (const int*)d_in[2];
    const float* W1     = (const float*)d_in[3];
    const float* b1     = (const float*)d_in[4];
    const float* Wc     = (const float*)d_in[5];
    const float* bc     = (const float*)d_in[6];
    const float* W2     = (const float*)d_in[7];
    const float* b2     = (const float*)d_in[8];
    const float* st     = (const float*)d_in[9];
    const float* et     = (const float*)d_in[10];
    const float* tr     = (const float*)d_in[11];
    float* out = (float*)d_out;

    (void)in_sizes; (void)n_in; (void)out_size;

    cudaFuncSetAttribute(emission_kernel,
                         cudaFuncAttributeMaxDynamicSharedMemorySize, SMEM_BYTES);

    dim3 tgrid(DIN / 32, DH / 32);
    w1_transpose_kernel<<<tgrid, dim3(32, 8)>>>(W1, out);

    dim3 egrid((T_DIM + TT - 1) / TT, BB);   // 17 x 32
    emission_kernel<<<egrid, 256, SMEM_BYTES>>>(x, b1, Wc, bc, W2, b2);

    crf_kernel<<<BB, 256>>>(mask, labels, st, et, tr, out);
}

// round 5
// speedup vs baseline: 3.7405x; 1.7171x over previous
#include <cuda_runtime.h>
#include <cuda_bf16.h>
#include <math.h>

#define BB    32
#define T_DIM 2048
#define DIN   1024
#define DH    64
#define DC    16
#define KW    7
#define NT    2

// Emission tiling
#define TT 122          // output timesteps per CTA
#define RR 128          // h1 rows per CTA (TT + 6 halo)
#define KC 64           // K chunk per smem stage

// All smem tiles use 32-bit-word pitch 36 (32 data words + 4 pad):
// fragment banks = 4*qr + qc + const  -> conflict-free for every access pattern.
#define P36 36
#define XS_OFF  0                         // [128][36] words (x tile / h1 tile, bf16x2)
#define WS_OFF  (RR * P36)                // [64][36]  words (W1 chunk, bf16x2)
#define WCS_OFF (WS_OFF + DH * P36)       // [7][16][36] words (conv weights, bf16x2)
#define SMEM_WORDS (WCS_OFF + KW * DC * P36)   // 10944 words = 43776 B (< 48KB static)

// Scratch (allocation-free rule: __device__ globals)
__device__ __align__(16) float g_emis[BB * T_DIM * 2];   // emissions [b][t][n]

// ---------------------------------------------------------------------------
// bf16 helpers
// ---------------------------------------------------------------------------
__device__ __forceinline__ unsigned pack_bf16(float lo, float hi) {
    unsigned r;
    asm("cvt.rn.bf16x2.f32 %0, %1, %2;" : "=r"(r) : "f"(hi), "f"(lo));
    return r;
}

__device__ __forceinline__ void mma_bf16(float* d,
                                         unsigned a0, unsigned a1, unsigned a2, unsigned a3,
                                         unsigned b0, unsigned b1) {
    asm volatile("mma.sync.aligned.m16n8k16.row.col.f32.bf16.bf16.f32 "
                 "{%0,%1,%2,%3}, {%4,%5,%6,%7}, {%8,%9}, {%0,%1,%2,%3};"
                 : "+f"(d[0]), "+f"(d[1]), "+f"(d[2]), "+f"(d[3])
                 : "r"(a0), "r"(a1), "r"(a2), "r"(a3), "r"(b0), "r"(b1));
}

// ---------------------------------------------------------------------------
// Kernel 1: fused emission, bf16 tensor-core GEMM + conv, register-prefetch
// pipelined k-chunks. One CTA = one (batch, 122-t tile). 256 threads, 8 warps.
// Warp w owns output rows [16w, 16w+16) x 64 cols.
// ---------------------------------------------------------------------------
__global__ void __launch_bounds__(256, 2)
emission_kernel(const float* __restrict__ x,
                const float* __restrict__ W1,
                const float* __restrict__ b1,
                const float* __restrict__ Wc,
                const float* __restrict__ bc,
                const float* __restrict__ W2,
                const float* __restrict__ b2,
                float* __restrict__ out)
{
    __shared__ unsigned sw[SMEM_WORDS];
    unsigned* xs  = sw + XS_OFF;
    unsigned* ws  = sw + WS_OFF;
    unsigned* wcs = sw + WCS_OFF;

    const int tid  = threadIdx.x;
    const int lane = tid & 31;
    const int warp = tid >> 5;
    const int qr   = lane >> 2;     // 0..7
    const int qc   = lane & 3;      // 0..3
    const int b    = blockIdx.y;
    const int t0   = blockIdx.x * TT;
    const int t_base = t0 - 3;
    const float* xb = x + (size_t)b * T_DIM * DIN;

    // zero the scalar output once (crf runs in a later kernel -> ordered)
    if (blockIdx.x == 0 && blockIdx.y == 0 && tid == 0) *out = 0.f;

    // ---- preload conv weights: wcs[k][c][hw] = pack(Wc[c][2hw][k], Wc[c][2hw+1][k])
    for (int d = tid; d < KW * DC * (DH / 2); d += 256) {
        int hw = d & 31;
        int c  = (d >> 5) & 15;
        int k  = d >> 9;
        float lo = __ldg(Wc + ((size_t)c * DH + 2 * hw)     * KW + k);
        float hi = __ldg(Wc + ((size_t)c * DH + 2 * hw + 1) * KW + k);
        wcs[(k * DC + c) * P36 + hw] = pack_bf16(lo, hi);
    }

    float acc[8][4];
#pragma unroll
    for (int j = 0; j < 8; j++)
#pragma unroll
        for (int i = 0; i < 4; i++) acc[j][i] = 0.f;

    // per-thread prefetch registers
    float4 px[8];   // x tile: 2048 float4 / 256 thr = 8
    float4 pw[4];   // W chunk: 1024 float4 / 256 thr = 4

    // thread -> tile coords (same for every chunk)
    const int xr = tid >> 4;            // base row (steps of 16 rows per it? no:)
    // x: idx = tid + it*256 -> r = idx>>4 in [0,128), q = idx&15
    // W: idx = tid + it*256 (it<4) -> h = idx>>4 in [0,64), q = idx&15
    (void)xr;

    // ---- prefetch chunk 0 ----
    {
        const int k0 = 0;
#pragma unroll
        for (int it = 0; it < 8; it++) {
            int idx = tid + it * 256;
            int r = idx >> 4, q = idx & 15;
            int t = t_base + r;
            px[it] = (t >= 0 && t < T_DIM)
                       ? *(const float4*)(xb + (size_t)t * DIN + k0 + q * 4)
                       : make_float4(0.f, 0.f, 0.f, 0.f);
        }
#pragma unroll
        for (int it = 0; it < 4; it++) {
            int idx = tid + it * 256;
            int h = idx >> 4, q = idx & 15;
            pw[it] = *(const float4*)(W1 + (size_t)h * DIN + k0 + q * 4);
        }
    }

    for (int c = 0; c < DIN / KC; c++) {
        __syncthreads();   // previous chunk's consumers done
        // ---- store prefetched chunk to smem as bf16x2 ----
#pragma unroll
        for (int it = 0; it < 8; it++) {
            int idx = tid + it * 256;
            int r = idx >> 4, q = idx & 15;
            float4 v = px[it];
            uint2 u = make_uint2(pack_bf16(v.x, v.y), pack_bf16(v.z, v.w));
            *(uint2*)(xs + r * P36 + 2 * q) = u;
        }
#pragma unroll
        for (int it = 0; it < 4; it++) {
            int idx = tid + it * 256;
            int h = idx >> 4, q = idx & 15;
            float4 v = pw[it];
            uint2 u = make_uint2(pack_bf16(v.x, v.y), pack_bf16(v.z, v.w));
            *(uint2*)(ws + h * P36 + 2 * q) = u;
        }
        __syncthreads();

        // ---- issue next chunk's global loads (latency hidden by MMAs) ----
        if (c + 1 < DIN / KC) {
            const int k0 = (c + 1) * KC;
#pragma unroll
            for (int it = 0; it < 8; it++) {
                int idx = tid + it * 256;
                int r = idx >> 4, q = idx & 15;
                int t = t_base + r;
                px[it] = (t >= 0 && t < T_DIM)
                           ? *(const float4*)(xb + (size_t)t * DIN + k0 + q * 4)
                           : make_float4(0.f, 0.f, 0.f, 0.f);
            }
#pragma unroll
            for (int it = 0; it < 4; it++) {
                int idx = tid + it * 256;
                int h = idx >> 4, q = idx & 15;
                pw[it] = *(const float4*)(W1 + (size_t)h * DIN + k0 + q * 4);
            }
        }

        // ---- 4 k16-steps of m16n8k16 ----
        const int r0 = warp * 16 + qr;
#pragma unroll
        for (int ks = 0; ks < KC / 16; ks++) {
            int kw = ks * 8;   // word base
            unsigned a0 = xs[r0 * P36 + kw + qc];
            unsigned a1 = xs[(r0 + 8) * P36 + kw + qc];
            unsigned a2 = xs[r0 * P36 + kw + qc + 4];
            unsigned a3 = xs[(r0 + 8) * P36 + kw + qc + 4];
#pragma unroll
            for (int j = 0; j < 8; j++) {
                unsigned b0 = ws[(j * 8 + qr) * P36 + kw + qc];
                unsigned b1r = ws[(j * 8 + qr) * P36 + kw + qc + 4];
                mma_bf16(acc[j], a0, a1, a2, a3, b0, b1r);
            }
        }
    }
    __syncthreads();   // last chunk's MMAs done before xs is overwritten

    // ---- GEMM epilogue: h1 = relu(acc + b1) stored to xs as bf16x2 ----
    {
        const int r0 = warp * 16 + qr;
        const int r1 = r0 + 8;
        const int tA = t_base + r0, tB = t_base + r1;
        const bool vA = (tA >= 0 && tA < T_DIM);
        const bool vB = (tB >= 0 && tB < T_DIM);
#pragma unroll
        for (int j = 0; j < 8; j++) {
            int c0 = j * 8 + 2 * qc, c1 = c0 + 1;
            float bv0 = __ldg(b1 + c0), bv1 = __ldg(b1 + c1);
            float hA0 = vA ? fmaxf(acc[j][0] + bv0, 0.f) : 0.f;
            float hA1 = vA ? fmaxf(acc[j][1] + bv1, 0.f) : 0.f;
            float hB0 = vB ? fmaxf(acc[j][2] + bv0, 0.f) : 0.f;
            float hB1 = vB ? fmaxf(acc[j][3] + bv1, 0.f) : 0.f;
            xs[r0 * P36 + 4 * j + qc] = pack_bf16(hA0, hA1);
            xs[r1 * P36 + 4 * j + qc] = pack_bf16(hB0, hB1);
        }
    }
    __syncthreads();

    // ---- conv as 7 shifted MMAs: D[r][c] = sum_k sum_h h1[r+k][h]*wc[k][h][c] ----
    float acc2[2][4];
#pragma unroll
    for (int j = 0; j < 2; j++)
#pragma unroll
        for (int i = 0; i < 4; i++) acc2[j][i] = 0.f;

    {
        const int wb2 = warp * 16;
#pragma unroll
        for (int k = 0; k < KW; k++) {
            const unsigned* wck = wcs + k * DC * P36;
            int ra = wb2 + k + qr;
            // rows >127 (feeding discarded outputs >=TT) read inside the smem
            // array (ws/wcs region) -> harmless garbage.
#pragma unroll
            for (int s = 0; s < DH / 16; s++) {
                int hw = s * 8;
                unsigned a0 = xs[ra * P36 + hw + qc];
                unsigned a1 = xs[(ra + 8) * P36 + hw + qc];
                unsigned a2 = xs[ra * P36 + hw + qc + 4];
                unsigned a3 = xs[(ra + 8) * P36 + hw + qc + 4];
#pragma unroll
                for (int j = 0; j < 2; j++) {
                    unsigned b0 = wck[(j * 8 + qr) * P36 + hw + qc];
                    unsigned b1r = wck[(j * 8 + qr) * P36 + hw + qc + 4];
                    mma_bf16(acc2[j], a0, a1, a2, a3, b0, b1r);
                }
            }
        }
    }

    // ---- +bc, relu, project 16->2, reduce across qc, store emissions ----
    {
        float e0a = 0.f, e1a = 0.f, e0b = 0.f, e1b = 0.f;
#pragma unroll
        for (int j = 0; j < 2; j++) {
            int c0 = j * 8 + 2 * qc, c1 = c0 + 1;
            float bc0 = __ldg(bc + c0), bc1 = __ldg(bc + c1);
            float w00 = __ldg(W2 + c0),      w01 = __ldg(W2 + c1);
            float w10 = __ldg(W2 + DC + c0), w11 = __ldg(W2 + DC + c1);
            float hA0 = fmaxf(acc2[j][0] + bc0, 0.f), hA1 = fmaxf(acc2[j][1] + bc1, 0.f);
            float hB0 = fmaxf(acc2[j][2] + bc0, 0.f), hB1 = fmaxf(acc2[j][3] + bc1, 0.f);
            e0a = fmaf(hA0, w00, fmaf(hA1, w01, e0a));
            e1a = fmaf(hA0, w10, fmaf(hA1, w11, e1a));
            e0b = fmaf(hB0, w00, fmaf(hB1, w01, e0b));
            e1b = fmaf(hB0, w10, fmaf(hB1, w11, e1b));
        }
#pragma unroll
        for (int m = 1; m <= 2; m <<= 1) {
            e0a += __shfl_xor_sync(0xffffffffu, e0a, m);
            e1a += __shfl_xor_sync(0xffffffffu, e1a, m);
            e0b += __shfl_xor_sync(0xffffffffu, e0b, m);
            e1b += __shfl_xor_sync(0xffffffffu, e1b, m);
        }
        if (qc == 0) {
            const float bz0 = __ldg(b2 + 0), bz1 = __ldg(b2 + 1);
            int rA = warp * 16 + qr, rB = rA + 8;
            if (rA < TT && t0 + rA < T_DIM)
                *(float2*)(g_emis + ((size_t)b * T_DIM + t0 + rA) * 2) =
                    make_float2(e0a + bz0, e1a + bz1);
            if (rB < TT && t0 + rB < T_DIM)
                *(float2*)(g_emis + ((size_t)b * T_DIM + t0 + rB) * 2) =
                    make_float2(e0b + bz0, e1b + bz1);
        }
    }
}

// ---------------------------------------------------------------------------
// Kernel 2: CRF NLL. One CTA per batch; forward scan = ordered product of 2x2
// log-semiring matrices -> tree reduction. Loads hoisted for MLP.
// ---------------------------------------------------------------------------
__device__ __forceinline__ float lse2(float a, float b) {
    float mx = fmaxf(a, b);
    float mn = fminf(a, b);
    return mx + log1pf(__expf(mn - mx));
}

__global__ void __launch_bounds__(256)
crf_kernel(const int* __restrict__ mask,
           const int* __restrict__ labels,
           const float* __restrict__ start_t,
           const float* __restrict__ end_t,
           const float* __restrict__ trans,
           float* __restrict__ out)
{
    __shared__ float sP[256][4];
    __shared__ float sNum[256];
    __shared__ int   sCnt[256];

    const int b = blockIdx.x, tid = threadIdx.x;
    const float* em = g_emis + (size_t)b * T_DIM * 2;
    const int* mk = mask + (size_t)b * T_DIM;
    const int* lb = labels + (size_t)b * T_DIM;

    const float t00 = trans[0], t01 = trans[1], t10 = trans[2], t11 = trans[3];

    // prefetch this thread's 8-timestep slab (batched loads -> MLP)
    const int s = 1 + tid * 8;
    float2 ev[8]; int mv[8], lv[8];
#pragma unroll
    for (int i = 0; i < 8; i++) {
        int t = s + i;
        bool ok = (t < T_DIM);
        mv[i] = ok ? mk[t] : 0;
        lv[i] = ok ? lb[t] : 0;
        ev[i] = ok ? ((const float2*)em)[t] : make_float2(0.f, 0.f);
    }
    int lprev = lb[s - 1];

    float P00 = 0.f, P01 = -1e30f, P10 = -1e30f, P11 = 0.f;  // identity
    float num = 0.f;
    int cnt = 0;

#pragma unroll
    for (int i = 0; i < 8; i++) {
        if (mv[i] != 0) {
            cnt++;
            int lc = lv[i];
            float tv = lprev ? (lc ? t11 : t10) : (lc ? t01 : t00);
            num += tv + (lc ? ev[i].y : ev[i].x);
            float M00 = t00 + ev[i].x, M01 = t01 + ev[i].y;
            float M10 = t10 + ev[i].x, M11 = t11 + ev[i].y;
            float c00 = lse2(P00 + M00, P01 + M10);
            float c01 = lse2(P00 + M01, P01 + M11);
            float c10 = lse2(P10 + M00, P11 + M10);
            float c11 = lse2(P10 + M01, P11 + M11);
            P00 = c00; P01 = c01; P10 = c10; P11 = c11;
        }
        lprev = lv[i];
    }

    sP[tid][0] = P00; sP[tid][1] = P01; sP[tid][2] = P10; sP[tid][3] = P11;
    sNum[tid] = num; sCnt[tid] = cnt;
    __syncthreads();

    for (int off = 128; off > 0; off >>= 1) {
        if (tid < off) {
            float A00 = sP[tid][0], A01 = sP[tid][1], A10 = sP[tid][2], A11 = sP[tid][3];
            float B00 = sP[tid + off][0], B01 = sP[tid + off][1];
            float B10 = sP[tid + off][2], B11 = sP[tid + off][3];
            sP[tid][0] = lse2(A00 + B00, A01 + B10);
            sP[tid][1] = lse2(A00 + B01, A01 + B11);
            sP[tid][2] = lse2(A10 + B00, A11 + B10);
            sP[tid][3] = lse2(A10 + B01, A11 + B11);
            sNum[tid] += sNum[tid + off];
            sCnt[tid] += sCnt[tid + off];
        }
        __syncthreads();
    }

    if (tid == 0) {
        float a0 = start_t[0] + em[0];
        float a1 = start_t[1] + em[1];
        float f0 = lse2(a0 + sP[0][0], a1 + sP[0][2]);
        float f1 = lse2(a0 + sP[0][1], a1 + sP[0][3]);
        float logZ = lse2(f0 + end_t[0], f1 + end_t[1]);

        int total = sCnt[0] + (mk[0] != 0 ? 1 : 0);
        int last = max(total - 1, 0);
        int l0 = lb[0];
        float numT = sNum[0] + start_t[l0] + (l0 ? em[1] : em[0]) + end_t[lb[last]];
        atomicAdd(out, logZ - numT);   // loss = sum_b (logZ - num)
    }
}

// ---------------------------------------------------------------------------
extern "C" void kernel_launch(void* const* d_in, const int* in_sizes, int n_in,
                              void* d_out, int out_size) {
    const float* x      = (const float*)d_in[0];
    const int*   mask   = (const int*)d_in[1];    // bool -> int32 per harness dtypes
    const int*   labels = (const int*)d_in[2];
    const float* W1     = (const float*)d_in[3];
    const float* b1     = (const float*)d_in[4];
    const float* Wc     = (const float*)d_in[5];
    const float* bc     = (const float*)d_in[6];
    const float* W2     = (const float*)d_in[7];
    const float* b2     = (const float*)d_in[8];
    const float* st     = (const float*)d_in[9];
    const float* et     = (const float*)d_in[10];
    const float* tr     = (const float*)d_in[11];
    float* out = (float*)d_out;

    (void)in_sizes; (void)n_in; (void)out_size;

    dim3 egrid((T_DIM + TT - 1) / TT, BB);   // 17 x 32
    emission_kernel<<<egrid, 256>>>(x, W1, b1, Wc, bc, W2, b2, out);

    crf_kernel<<<BB, 256>>>(mask, labels, st, et, tr, out);
}